// round 16
// baseline (speedup 1.0000x reference)
#include <cuda_runtime.h>
#include <cuda_fp16.h>
#include <cstdint>

// Shapes (fixed): B=8, S=4096, E=512 -> M=32768, N=K=512
#define M_TOT 32768
#define N_TOT 512
#define K_TOT 512

#define BM 128
#define BN 128
#define BK 64                 // halves; 4 k-slices of k16 per chunk
#define NTH 128               // 4 warps, 2(m) x 2(n), warp tile 64x64
#define NCH (K_TOT / BK)      // 8
#define NSTAGE 3

// smem rows: 64 data halves (128B) + 8 pad halves (16B) = 144B/row.
#define RB 144
#define B_OFF (128 * RB)
#define STG_B (2 * 128 * RB)              // 36864 B / stage
#define SMEM_BYTES (NSTAGE * STG_B)       // 110592 B -> 2 CTAs/SM

// ---------------- scratch (device globals: sanctioned no-alloc path) ----------
__device__ __half g_Vh[(size_t)M_TOT * K_TOT];
__device__ __half g_V [(size_t)M_TOT * N_TOT];
__device__ __half g_Vc[(size_t)M_TOT * N_TOT];
__device__ __half g_Wa[(size_t)N_TOT * K_TOT];
__device__ __half g_Wb[(size_t)N_TOT * K_TOT];

__device__ __forceinline__ uint32_t smem_u32(const void* p) {
    uint32_t a;
    asm("{ .reg .u64 t; cvta.to.shared.u64 t, %1; cvt.u32.u64 %0, t; }" : "=r"(a) : "l"(p));
    return a;
}
__device__ __forceinline__ void cp16(uint32_t saddr, const void* gptr) {
    asm volatile("cp.async.cg.shared.global [%0], [%1], 16;"
                 :: "r"(saddr), "l"(gptr) : "memory");
}
__device__ __forceinline__ void ldsm4(uint32_t* r, uint32_t addr) {
    asm volatile("ldmatrix.sync.aligned.m8n8.x4.shared.b16 {%0,%1,%2,%3}, [%4];"
                 : "=r"(r[0]), "=r"(r[1]), "=r"(r[2]), "=r"(r[3]) : "r"(addr));
}
__device__ __forceinline__ void mma16(float* c, const uint32_t* a,
                                      uint32_t b0, uint32_t b1) {
    asm volatile(
        "mma.sync.aligned.m16n8k16.row.col.f32.f16.f16.f32 "
        "{%0,%1,%2,%3}, {%4,%5,%6,%7}, {%8,%9}, {%0,%1,%2,%3};"
        : "+f"(c[0]), "+f"(c[1]), "+f"(c[2]), "+f"(c[3])
        : "r"(a[0]), "r"(a[1]), "r"(a[2]), "r"(a[3]), "r"(b0), "r"(b1));
}

// C[m,n] = sum_k A[m,k]*B[n,k]; A,B fp16 row-major [.,K]; fp32 acc.
// 64x64 warp tiles, 2 CTAs/SM, static double-buffered fragments.
// Chunk boundary reordered: barrier -> LDSM+MMA first, cp.async burst after,
// so the tensor pipe restarts immediately after each sync.
template <bool HALF_OUT>
__global__ __launch_bounds__(NTH, 2)
void gemm_h16(const __half* __restrict__ A,
              const __half* __restrict__ B,
              void* __restrict__ Cv)
{
    extern __shared__ char sm[];
    const uint32_t sb = smem_u32(sm);
    const int tid  = threadIdx.x;
    const int wid  = tid >> 5;
    const int lane = tid & 31;
    const int wm   = wid >> 1;
    const int wn   = wid & 1;
    const int lr   = lane >> 2;
    const int lc   = lane & 3;
    const int bm   = blockIdx.y * BM;
    const int bn   = blockIdx.x * BN;
    const int grp  = lane >> 3;
    const int lr8  = lane & 7;

    const uint4* Ag = (const uint4*)(A + (size_t)bm * K_TOT);
    const uint4* Bg = (const uint4*)(B + (size_t)bn * K_TOT);

    const uint32_t laneA = (uint32_t)(((grp & 1) * 8 + lr8) * RB + (grp >> 1) * 16);
    const uint32_t laneB = (uint32_t)(((grp >> 1) * 8 + lr8) * RB + (grp & 1) * 16);

    auto issue = [&](int c) {
        const int s = c % NSTAGE;
        const uint32_t sa  = sb + (uint32_t)(s * STG_B);
        const uint32_t sbB = sa + (uint32_t)B_OFF;
        #pragma unroll
        for (int i = 0; i < 8; i++) {
            int f = tid + i * NTH, m = f >> 3, q = f & 7;
            cp16(sa + (uint32_t)(m * RB + q * 16),
                 Ag + (size_t)m * (K_TOT / 8) + c * 8 + q);
        }
        #pragma unroll
        for (int i = 0; i < 8; i++) {
            int f = tid + i * NTH, n = f >> 3, q = f & 7;
            cp16(sbB + (uint32_t)(n * RB + q * 16),
                 Bg + (size_t)n * (K_TOT / 8) + c * 8 + q);
        }
        asm volatile("cp.async.commit_group;" ::: "memory");
    };

    uint32_t af0[4][4], bf0[4][4];
    uint32_t af1[4][4], bf1[4][4];

    float acc[4][8][4];
    #pragma unroll
    for (int a = 0; a < 4; a++)
        #pragma unroll
        for (int b = 0; b < 8; b++)
            #pragma unroll
            for (int r = 0; r < 4; r++) acc[a][b][r] = 0.0f;

    #define ABASE(c, ks) (sb + (uint32_t)(((c) % NSTAGE) * STG_B)               \
                          + (uint32_t)(wm * 64 * RB) + laneA + (uint32_t)(ks) * 32u)
    #define BBASE(c, ks) (sb + (uint32_t)(((c) % NSTAGE) * STG_B) + (uint32_t)B_OFF \
                          + (uint32_t)(wn * 64 * RB) + laneB + (uint32_t)(ks) * 32u)

    #define MMAROW(AF, BF, mt)                                                 \
        do {                                                                   \
            _Pragma("unroll")                                                  \
            for (int nt = 0; nt < 8; nt++) {                                   \
                uint32_t b0_ = BF[nt >> 1][(nt & 1) * 2 + 0];                  \
                uint32_t b1_ = BF[nt >> 1][(nt & 1) * 2 + 1];                  \
                mma16(acc[mt][nt], AF[mt], b0_, b1_);                          \
            }                                                                  \
        } while (0)

    // consume (CA,CB); prefetch slice (cn,ksn) into (NA,NB), interleaved
    #define SLICE_INT(CA, CB, cn, ksn, NA, NB)                                 \
        do {                                                                   \
            const uint32_t aB_ = ABASE(cn, ksn);                               \
            const uint32_t bB_ = BBASE(cn, ksn);                               \
            ldsm4(NA[0], aB_);                                                 \
            ldsm4(NA[1], aB_ + (uint32_t)(16 * RB));                           \
            MMAROW(CA, CB, 0);                                                 \
            ldsm4(NA[2], aB_ + (uint32_t)(32 * RB));                           \
            ldsm4(NA[3], aB_ + (uint32_t)(48 * RB));                           \
            MMAROW(CA, CB, 1);                                                 \
            ldsm4(NB[0], bB_);                                                 \
            ldsm4(NB[1], bB_ + (uint32_t)(16 * RB));                           \
            MMAROW(CA, CB, 2);                                                 \
            ldsm4(NB[2], bB_ + (uint32_t)(32 * RB));                           \
            ldsm4(NB[3], bB_ + (uint32_t)(48 * RB));                           \
            MMAROW(CA, CB, 3);                                                 \
        } while (0)

    #define SLICE_LAST(CA, CB)                                                 \
        do { MMAROW(CA, CB, 0); MMAROW(CA, CB, 1);                             \
             MMAROW(CA, CB, 2); MMAROW(CA, CB, 3); } while (0)

    #define PF0(c, AF, BF)                                                     \
        do {                                                                   \
            const uint32_t aB_ = ABASE(c, 0);                                  \
            const uint32_t bB_ = BBASE(c, 0);                                  \
            _Pragma("unroll")                                                  \
            for (int mt = 0; mt < 4; mt++)                                     \
                ldsm4(AF[mt], aB_ + (uint32_t)(mt * 16 * RB));                 \
            _Pragma("unroll")                                                  \
            for (int p = 0; p < 4; p++)                                        \
                ldsm4(BF[p], bB_ + (uint32_t)(p * 16 * RB));                   \
        } while (0)

    // prologue
    issue(0);
    issue(1);
    asm volatile("cp.async.wait_group 1;" ::: "memory");   // my g0 done
    __syncthreads();                                       // everyone's g0 visible
    issue(2);
    PF0(0, af0, bf0);

    for (int c = 0; c < NCH; c++) {
        SLICE_INT(af0, bf0, c, 1, af1, bf1);   // consume s0, prefetch s1
        SLICE_INT(af1, bf1, c, 2, af0, bf0);   // consume s1, prefetch s2
        SLICE_INT(af0, bf0, c, 3, af1, bf1);   // consume s2, prefetch s3
        // all reads of stage c%3 are done (s3 fragments in registers)
        if (c + 1 < NCH) {
            // committed: 0..c+2; wait_group 1 -> my g(c+1) complete
            asm volatile("cp.async.wait_group 1;" ::: "memory");
            __syncthreads();                   // publish g(c+1); stage c%3 free
            // LDSM+MMA first so tensor pipe restarts immediately ...
            SLICE_INT(af1, bf1, c + 1, 0, af0, bf0);  // consume s3, prefetch s0'
            // ... then the cp.async burst (2-chunk slack before its wait)
            if (c + 3 < NCH) issue(c + 3);
            else asm volatile("cp.async.commit_group;" ::: "memory");
        } else {
            SLICE_LAST(af1, bf1);
        }
    }

    // ---- epilogue ----
    #pragma unroll
    for (int mt = 0; mt < 4; mt++) {
        int m = bm + wm * 64 + mt * 16 + lr;
        if (HALF_OUT) {
            __half* crow = (__half*)Cv + (size_t)m * N_TOT + bn + wn * 64;
            #pragma unroll
            for (int nt = 0; nt < 8; nt++) {
                int nf = nt * 8 + lc * 2;
                *(__half2*)(crow + nf) =
                    __floats2half2_rn(acc[mt][nt][0], acc[mt][nt][1]);
                *(__half2*)(crow + nf + (size_t)8 * N_TOT) =
                    __floats2half2_rn(acc[mt][nt][2], acc[mt][nt][3]);
            }
        } else {
            float* crow = (float*)Cv + (size_t)m * N_TOT + bn + wn * 64;
            #pragma unroll
            for (int nt = 0; nt < 8; nt++) {
                int nf = nt * 8 + lc * 2;
                *(float2*)(crow + nf) = make_float2(acc[mt][nt][0], acc[mt][nt][1]);
                *(float2*)(crow + nf + (size_t)8 * N_TOT) =
                    make_float2(acc[mt][nt][2], acc[mt][nt][3]);
            }
        }
    }
    #undef ABASE
    #undef BBASE
    #undef MMAROW
    #undef SLICE_INT
    #undef SLICE_LAST
    #undef PF0
}

// ------------- fp32 -> fp16 convert, 32 elems/thread (MLP 8) ----------------
__global__ void f2h32_kernel(const float4* __restrict__ in, uint4* __restrict__ out)
{
    int i = blockIdx.x * 256 + threadIdx.x;
    #pragma unroll
    for (int h = 0; h < 2; h++) {
        float4 a = in[8 * i + 4 * h + 0], b = in[8 * i + 4 * h + 1];
        float4 c = in[8 * i + 4 * h + 2], d = in[8 * i + 4 * h + 3];
        __half2 h0 = __floats2half2_rn(a.x, a.y), h1 = __floats2half2_rn(a.z, a.w);
        __half2 h2 = __floats2half2_rn(b.x, b.y), h3 = __floats2half2_rn(b.z, b.w);
        __half2 h4 = __floats2half2_rn(c.x, c.y), h5 = __floats2half2_rn(c.z, c.w);
        __half2 h6 = __floats2half2_rn(d.x, d.y), h7 = __floats2half2_rn(d.z, d.w);
        uint4 o0, o1;
        o0.x = *(uint32_t*)&h0; o0.y = *(uint32_t*)&h1;
        o0.z = *(uint32_t*)&h2; o0.w = *(uint32_t*)&h3;
        o1.x = *(uint32_t*)&h4; o1.y = *(uint32_t*)&h5;
        o1.z = *(uint32_t*)&h6; o1.w = *(uint32_t*)&h7;
        out[4 * i + 2 * h + 0] = o0;
        out[4 * i + 2 * h + 1] = o1;
    }
}

// ---- both weight matrices in one launch (each 256K floats) ------------------
__global__ void f2h_weights_kernel(const float4* __restrict__ wa,
                                   const float4* __restrict__ wb,
                                   uint4* __restrict__ oa,
                                   uint4* __restrict__ ob)
{
    int i = blockIdx.x * 256 + threadIdx.x;          // 32768 threads, 2 f4 each
    const float4* src = (i < 32768) ? wa : wb;
    uint4* dst        = (i < 32768) ? oa : ob;
    int j = i & 32767;
    float4 a = src[2 * j], b = src[2 * j + 1];
    __half2 h0 = __floats2half2_rn(a.x, a.y), h1 = __floats2half2_rn(a.z, a.w);
    __half2 h2 = __floats2half2_rn(b.x, b.y), h3 = __floats2half2_rn(b.z, b.w);
    uint4 o;
    o.x = *(uint32_t*)&h0; o.y = *(uint32_t*)&h1;
    o.z = *(uint32_t*)&h2; o.w = *(uint32_t*)&h3;
    dst[j] = o;
}

// ---- 5-tap Gaussian window, per-head shift {0,-1,+1,0}x2; fp16 in/out -------
__global__ void conv_h_kernel(const __half* __restrict__ V, __half* __restrict__ Vc)
{
    int idx = blockIdx.x * blockDim.x + threadIdx.x;   // M_TOT*64 threads
    int c8  = idx & 63;
    int m   = idx >> 6;
    int s   = m & 4095;
    int mb0 = m - s;
    int hm  = (c8 >> 3) & 3;
    int shift = (hm == 1) ? -1 : ((hm == 2) ? 1 : 0);

    const float F[5] = {0.05399096651318806f, 0.24197072451914337f,
                        0.3989422804014327f,  0.24197072451914337f,
                        0.05399096651318806f};

    float a[8];
    #pragma unroll
    for (int e = 0; e < 8; e++) a[e] = 0.0f;

    const uint4* V4 = (const uint4*)V;
    #pragma unroll
    for (int j = 0; j < 5; j++) {
        int ss = s + shift + j - 2;
        if (ss >= 0 && ss < 4096) {
            uint4 v = V4[(size_t)(mb0 + ss) * 64 + c8];
            __half2 p0 = *(__half2*)&v.x, p1 = *(__half2*)&v.y;
            __half2 p2 = *(__half2*)&v.z, p3 = *(__half2*)&v.w;
            float2 f0 = __half22float2(p0), f1 = __half22float2(p1);
            float2 f2 = __half22float2(p2), f3 = __half22float2(p3);
            a[0] += F[j] * f0.x; a[1] += F[j] * f0.y;
            a[2] += F[j] * f1.x; a[3] += F[j] * f1.y;
            a[4] += F[j] * f2.x; a[5] += F[j] * f2.y;
            a[6] += F[j] * f3.x; a[7] += F[j] * f3.y;
        }
    }
    __half2 o0 = __floats2half2_rn(a[0], a[1]);
    __half2 o1 = __floats2half2_rn(a[2], a[3]);
    __half2 o2 = __floats2half2_rn(a[4], a[5]);
    __half2 o3 = __floats2half2_rn(a[6], a[7]);
    uint4 o;
    o.x = *(uint32_t*)&o0; o.y = *(uint32_t*)&o1;
    o.z = *(uint32_t*)&o2; o.w = *(uint32_t*)&o3;
    ((uint4*)Vc)[idx] = o;
}

// ---------------- launcher ----------------
extern "C" void kernel_launch(void* const* d_in, const int* in_sizes, int n_in,
                              void* d_out, int out_size)
{
    const float* values = (const float*)d_in[0];
    const float* win    = (const float*)d_in[3];
    const float* wout   = (const float*)d_in[4];
    float*       out    = (float*)d_out;

    __half *pVh, *pV, *pVc, *pWa, *pWb;
    cudaGetSymbolAddress((void**)&pVh, g_Vh);
    cudaGetSymbolAddress((void**)&pV,  g_V);
    cudaGetSymbolAddress((void**)&pVc, g_Vc);
    cudaGetSymbolAddress((void**)&pWa, g_Wa);
    cudaGetSymbolAddress((void**)&pWb, g_Wb);

    cudaFuncSetAttribute(gemm_h16<true>,
                         cudaFuncAttributeMaxDynamicSharedMemorySize, SMEM_BYTES);
    cudaFuncSetAttribute(gemm_h16<false>,
                         cudaFuncAttributeMaxDynamicSharedMemorySize, SMEM_BYTES);

    dim3 grid(N_TOT / BN, M_TOT / BM);   // (4, 256)

    // values: 16M floats / 32 per thread = 524288 threads = 2048 blocks
    f2h32_kernel<<<(M_TOT * K_TOT / 32) / 256, 256>>>((const float4*)values,
                                                      (uint4*)pVh);
    // both weight matrices in one launch: 65536 threads
    f2h_weights_kernel<<<256, 256>>>((const float4*)win, (const float4*)wout,
                                     (uint4*)pWa, (uint4*)pWb);

    gemm_h16<true ><<<grid, NTH, SMEM_BYTES>>>(pVh, pWa, pV);
    conv_h_kernel<<<(M_TOT * 64) / 256, 256>>>(pV, pVc);
    gemm_h16<false><<<grid, NTH, SMEM_BYTES>>>(pVc, pWb, out);
}